// round 9
// baseline (speedup 1.0000x reference)
#include <cuda_runtime.h>

// ContConv1dDenseSim: out[b,l,o] = sum_{j in band, i} feat[b,j,i] * kv(dt_{l,j})[i,o]
// kv = MLP(relu) on scalar dt; banded causal mask (width 30); true_ids column mask;
// row-validity l <= 6*(len-1).
//
// Refactor (exact): FW2[j,h,o] = sum_i feat[j,i]*w2[h,i*16+o]; FB2[j,o] = sum_i feat[j,i]*b2[i*16+o]
// out[l,o] = sum_{j in band} ( FB2[j,o] + sum_h relu(dt*w1_h + b1_h) * FW2[j,h,o] )
//
// R9: fixed-trip predicated unrolls. Phase 1: exactly 5 rows/group (jr=5g+u, pred jr<nj).
// Phase 2: exactly 4 band elems/group (jr=jr_lo+4g+u, pred jr<=lr). Compile-time
// trip counts -> full unroll, back-to-back LDS, no loop ALU. R8 load schedule kept.

namespace cc {
constexpr int LEN     = 512;
constexpr int BSZ     = 2;
constexpr int IN_CH   = 16;
constexpr int OUT_CH  = 16;
constexpr int HID     = 8;
constexpr int BAND    = 30;                 // j in [l-29, l]
constexpr int TILE_L  = 8;
constexpr int NJMAX   = BAND - 1 + TILE_L;  // 37
constexpr int OSTR    = 12;                 // 8 FW2 + FB2 + pad (16B aligned)
constexpr int JSTR    = OUT_CH * OSTR;      // 192 floats per jr row
constexpr int W2STR   = 272;                // padded w2 row (16h offset -> bank-split)
constexpr int NTHR    = 1024;
constexpr int NGRP    = 8;
}

__global__ __launch_bounds__(1024, 1)
void cc1d_fused_kernel(const float* __restrict__ times,
                       const float* __restrict__ features,
                       const int* __restrict__ lengths_i32,   // int32 or int64 layout
                       const void* __restrict__ true_ids_raw, // u8 or int32 layout
                       const float* __restrict__ w1,
                       const float* __restrict__ b1,
                       const float* __restrict__ w2,
                       const float* __restrict__ b2,
                       float* __restrict__ out)
{
    using namespace cc;
    __shared__ __align__(16) float feats[NJMAX * IN_CH];
    __shared__ __align__(16) float fw2s[NJMAX * JSTR];
    __shared__ __align__(16) float w2s[HID * W2STR];
    __shared__ __align__(16) float b2s[IN_CH * OUT_CH];      // [i*16+o]
    __shared__ float ts[NJMAX];
    __shared__ float w1s[HID], b1s[HID];
    __shared__ float partial[(NGRP - 1) * 128];

    const int b       = blockIdx.y;
    const int l_start = blockIdx.x * TILE_L;
    const int t       = threadIdx.x;
    const int g       = t >> 7;         // work-split group 0..7
    const int m       = t & 127;
    const int h       = m >> 4;         // hidden unit (phase1) / l_local (phase2)
    const int o       = m & 15;
    const int lane    = t & 31;

    int j0 = l_start - (BAND - 1); if (j0 < 0) j0 = 0;
    const int nj = (l_start + TILE_L - 1) - j0 + 1;   // <= NJMAX

    // ---- (1) barrier-critical loads FIRST: feats float4 (<=148 threads, 1 iter) ----
    float4 fv = make_float4(0.f, 0.f, 0.f, 0.f);
    const int jr_f = t >> 2;
    const int j_f  = j0 + jr_f;
    const bool do_feat = (t < nj * 4);
    if (do_feat)
        fv = ((const float4*)features)[(b * LEN + j_f) * 4 + (t & 3)];

    // ---- (2) layout detection: 1 LDG/thread over first 128B (L2/L1-shared).
    // int32-bool values are 0/1 => any nonzero byte above byte-0 => byte layout.
    const unsigned int v0 = ((const unsigned int*)true_ids_raw)[lane];

    // ---- (3) other cooperative loads (contiguous, few wavefronts) ----
    if (t < 512) {   // w2: 2048 floats as float4 into padded-stride shared
        const float4 wv = ((const float4*)w2)[t];
        const int hh = t >> 6, c4 = t & 63;
        *(float4*)&w2s[hh * W2STR + c4 * 4] = wv;
    }
    else if (t < 512 + 64) {  // b2: 256 floats as float4
        ((float4*)b2s)[t - 512] = ((const float4*)b2)[t - 512];
    }
    else if (t < 576 + HID) { w1s[t - 576] = w1[t - 576]; b1s[t - 576] = b1[t - 576]; }
    else if (t >= 640 && t - 640 < nj) ts[t - 640] = times[b * LEN + j0 + (t - 640)];

    int len_pref = 0;   // only g==0 stores output; avoid 2048 junk LDGs
    if (t < 128) {
        const int hw = __ldg(&lengths_i32[1]);   // hi word 0 <=> int64 (lengths >= 1)
        len_pref = (hw == 0) ? __ldg(&lengths_i32[2 * b]) : __ldg(&lengths_i32[b]);
    }

    // ---- resolve detection, fetch mask byte, select, store feats ----
    const bool byte_layout =
        __ballot_sync(0xFFFFFFFFu, (v0 & 0xFFFFFF00u) != 0u) != 0u;
    if (do_feat) {
        // LSB byte of an int32 bool equals its value (little-endian)
        const int bidx = (b * LEN + j_f) << (byte_layout ? 0 : 2);
        if (((const unsigned char*)true_ids_raw)[bidx] == 0)
            fv = make_float4(0.f, 0.f, 0.f, 0.f);
        ((float4*)feats)[t] = fv;
    }
    __syncthreads();   // feats, ts, w1s, b2s, w2s visible

    // per-thread w2 column from shared (conflict-free: 16h offset splits halves)
    float w2col[IN_CH];
    #pragma unroll
    for (int i = 0; i < IN_CH; i++)
        w2col[i] = w2s[h * W2STR + i * 16 + o];

    // ---- phase 1: FW2/FB2 transposed store; fixed 5 predicated rows per group ----
    {
        const int jr_base = g * 5;
        #pragma unroll
        for (int u = 0; u < 5; u++) {
            const int jr = jr_base + u;
            if (jr < nj) {
                const float4* fj4 = (const float4*)&feats[jr * IN_CH];
                float4 fa = fj4[0], fb = fj4[1], fc = fj4[2], fd = fj4[3];
                float aA = 0.0f, aB = 0.0f;
                aA = fmaf(fa.x, w2col[0], aA); aB = fmaf(fb.x, w2col[4], aB);
                aA = fmaf(fa.y, w2col[1], aA); aB = fmaf(fb.y, w2col[5], aB);
                aA = fmaf(fa.z, w2col[2], aA); aB = fmaf(fb.z, w2col[6], aB);
                aA = fmaf(fa.w, w2col[3], aA); aB = fmaf(fb.w, w2col[7], aB);
                aA = fmaf(fc.x, w2col[8],  aA); aB = fmaf(fd.x, w2col[12], aB);
                aA = fmaf(fc.y, w2col[9],  aA); aB = fmaf(fd.y, w2col[13], aB);
                aA = fmaf(fc.z, w2col[10], aA); aB = fmaf(fd.z, w2col[14], aB);
                aA = fmaf(fc.w, w2col[11], aA); aB = fmaf(fd.w, w2col[15], aB);
                fw2s[jr * JSTR + o * OSTR + h] = aA + aB;
                if (h == (jr & 7)) {       // one o-row of threads per jr does FB2
                    float bA = 0.0f, bB = 0.0f;
                    bA = fmaf(fa.x, b2s[0 * 16 + o],  bA); bB = fmaf(fb.x, b2s[4 * 16 + o],  bB);
                    bA = fmaf(fa.y, b2s[1 * 16 + o],  bA); bB = fmaf(fb.y, b2s[5 * 16 + o],  bB);
                    bA = fmaf(fa.z, b2s[2 * 16 + o],  bA); bB = fmaf(fb.z, b2s[6 * 16 + o],  bB);
                    bA = fmaf(fa.w, b2s[3 * 16 + o],  bA); bB = fmaf(fb.w, b2s[7 * 16 + o],  bB);
                    bA = fmaf(fc.x, b2s[8 * 16 + o],  bA); bB = fmaf(fd.x, b2s[12 * 16 + o], bB);
                    bA = fmaf(fc.y, b2s[9 * 16 + o],  bA); bB = fmaf(fd.y, b2s[13 * 16 + o], bB);
                    bA = fmaf(fc.z, b2s[10 * 16 + o], bA); bB = fmaf(fd.z, b2s[14 * 16 + o], bB);
                    bA = fmaf(fc.w, b2s[11 * 16 + o], bA); bB = fmaf(fd.w, b2s[15 * 16 + o], bB);
                    fw2s[jr * JSTR + o * OSTR + 8] = bA + bB;
                }
            }
        }
    }
    __syncthreads();

    // ---- phase 2: band reduction per (l, o); fixed 4 predicated elems per group ----
    const int l  = l_start + h;      // h == l_local here
    const int lr = l - j0;
    const float tl = ts[lr];

    float w1r[HID], b1r[HID];
    #pragma unroll
    for (int k = 0; k < HID; k++) { w1r[k] = w1s[k]; b1r[k] = b1s[k]; }

    int jr_lo = lr - (BAND - 1); if (jr_lo < 0) jr_lo = 0;
    const int js = jr_lo + g * 4;    // band <= 30 wide, 8 groups x 4 covers it

    float acc0 = 0.0f, acc1 = 0.0f;
    #pragma unroll
    for (int u = 0; u < 4; u++) {
        const int jr = js + u;
        if (jr <= lr) {
            const float dt = tl - ts[jr];
            const float* frp = &fw2s[jr * JSTR + o * OSTR];
            const float4 fA = *(const float4*)frp;        // FW2 h=0..3
            const float4 fB = *(const float4*)(frp + 4);  // FW2 h=4..7
            float a0 = frp[8];                            // FB2 term
            float a1 = 0.0f;
            float hv;
            hv = fmaf(dt, w1r[0], b1r[0]); hv = hv > 0.f ? hv : 0.f; a0 = fmaf(hv, fA.x, a0);
            hv = fmaf(dt, w1r[1], b1r[1]); hv = hv > 0.f ? hv : 0.f; a1 = fmaf(hv, fA.y, a1);
            hv = fmaf(dt, w1r[2], b1r[2]); hv = hv > 0.f ? hv : 0.f; a0 = fmaf(hv, fA.z, a0);
            hv = fmaf(dt, w1r[3], b1r[3]); hv = hv > 0.f ? hv : 0.f; a1 = fmaf(hv, fA.w, a1);
            hv = fmaf(dt, w1r[4], b1r[4]); hv = hv > 0.f ? hv : 0.f; a0 = fmaf(hv, fB.x, a0);
            hv = fmaf(dt, w1r[5], b1r[5]); hv = hv > 0.f ? hv : 0.f; a1 = fmaf(hv, fB.y, a1);
            hv = fmaf(dt, w1r[6], b1r[6]); hv = hv > 0.f ? hv : 0.f; a0 = fmaf(hv, fB.z, a0);
            hv = fmaf(dt, w1r[7], b1r[7]); hv = hv > 0.f ? hv : 0.f; a1 = fmaf(hv, fB.w, a1);
            acc0 += a0; acc1 += a1;
        }
    }
    float acc = acc0 + acc1;

    if (g > 0) partial[(g - 1) * 128 + m] = acc;
    __syncthreads();

    if (g == 0) {
        float p0 = partial[m]           + partial[128 + m];
        float p1 = partial[2 * 128 + m] + partial[3 * 128 + m];
        float p2 = partial[4 * 128 + m] + partial[5 * 128 + m];
        acc += (p0 + p1) + (p2 + partial[6 * 128 + m]);
        const bool valid = l <= 6 * (len_pref - 1);
        out[(b * LEN + l) * OUT_CH + o] = valid ? acc : 0.0f;
    }
}

extern "C" void kernel_launch(void* const* d_in, const int* in_sizes, int n_in,
                              void* d_out, int out_size) {
    using namespace cc;
    // dict order: times, features, lengths, true_ids, [sim_size], w1, b1, w2, b2
    const float* times    = (const float*)d_in[0];
    const float* features = (const float*)d_in[1];
    const int*   lengths  = (const int*)d_in[2];
    const void*  tids     = d_in[3];

    int base = 4;
    if (n_in >= 9 && in_sizes[4] == 1) base = 5;  // sim_size scalar occupies slot 4

    const float* w1 = (const float*)d_in[base + 0];
    const float* b1 = (const float*)d_in[base + 1];
    const float* w2 = (const float*)d_in[base + 2];
    const float* b2 = (const float*)d_in[base + 3];
    float*       out = (float*)d_out;

    dim3 grid(LEN / TILE_L, BSZ);   // 64 x 2 = 128 blocks, 1 per SM
    cc1d_fused_kernel<<<grid, NTHR>>>(times, features, lengths, tids,
                                      w1, b1, w2, b2, out);
}

// round 12
// speedup vs baseline: 1.0257x; 1.0257x over previous
#include <cuda_runtime.h>

// ContConv1dDenseSim: out[b,l,o] = sum_{j in band, i} feat[b,j,i] * kv(dt_{l,j})[i,o]
// kv = MLP(relu) on scalar dt; banded causal mask (width 30); true_ids column mask;
// row-validity l <= 6*(len-1).
//
// Refactor (exact): FW2[j,h,o] = sum_i feat[j,i]*w2[h,i*16+o]; FB2[j,o] = sum_i feat[j,i]*b2[i*16+o]
// out[l,o] = sum_{j in band} ( FB2[j,o] + sum_h relu(dt*w1_h + b1_h) * FW2[j,h,o] )
//
// R11 == R10 resubmit (infra failure, no signal). Block specialization: for
// blockIdx.x >= 4 the band never clips: nj == 37, lr == h+29, band exactly 30 ->
// compile-time trip counts and immediate shared offsets (R9 post-mortem showed
// runtime bases bloat SASS ~2x). Edge blocks (bx < 4) take the generic path
// behind a block-uniform branch; single launch.

namespace cc {
constexpr int LEN     = 512;
constexpr int BSZ     = 2;
constexpr int IN_CH   = 16;
constexpr int OUT_CH  = 16;
constexpr int HID     = 8;
constexpr int BAND    = 30;                 // j in [l-29, l]
constexpr int TILE_L  = 8;
constexpr int NJMAX   = BAND - 1 + TILE_L;  // 37
constexpr int OSTR    = 12;                 // 8 FW2 + FB2 + pad (16B aligned)
constexpr int JSTR    = OUT_CH * OSTR;      // 192 floats per jr row
constexpr int W2STR   = 272;                // padded w2 row (16h offset -> bank-split)
constexpr int NTHR    = 1024;
constexpr int NGRP    = 8;
}

__global__ __launch_bounds__(1024, 1)
void cc1d_fused_kernel(const float* __restrict__ times,
                       const float* __restrict__ features,
                       const int* __restrict__ lengths_i32,   // int32 or int64 layout
                       const void* __restrict__ true_ids_raw, // u8 or int32 layout
                       const float* __restrict__ w1,
                       const float* __restrict__ b1,
                       const float* __restrict__ w2,
                       const float* __restrict__ b2,
                       float* __restrict__ out)
{
    using namespace cc;
    __shared__ __align__(16) float feats[NJMAX * IN_CH];
    __shared__ __align__(16) float fw2s[NJMAX * JSTR];
    __shared__ __align__(16) float w2s[HID * W2STR];
    __shared__ __align__(16) float b2s[IN_CH * OUT_CH];      // [i*16+o]
    __shared__ float ts[NJMAX];
    __shared__ float w1s[HID], b1s[HID];
    __shared__ float partial[(NGRP - 1) * 128];

    const int b       = blockIdx.y;
    const int l_start = blockIdx.x * TILE_L;
    const bool FULL   = (blockIdx.x >= 4);    // band never clips: j0=l_start-29, nj=37
    const int t       = threadIdx.x;
    const int g       = t >> 7;         // work-split group 0..7 (warp-uniform)
    const int m       = t & 127;
    const int h       = m >> 4;         // hidden unit (phase1) / l_local (phase2)
    const int o       = m & 15;
    const int lane    = t & 31;

    const int j0 = FULL ? (l_start - (BAND - 1)) : 0;
    const int nj = FULL ? NJMAX : (l_start + TILE_L);

    // ---- (1) barrier-critical loads FIRST: feats float4 (<=148 threads, 1 iter) ----
    float4 fv = make_float4(0.f, 0.f, 0.f, 0.f);
    const int jr_f = t >> 2;
    const int j_f  = j0 + jr_f;
    const bool do_feat = (t < nj * 4);
    if (do_feat)
        fv = ((const float4*)features)[(b * LEN + j_f) * 4 + (t & 3)];

    // ---- (2) layout detection: 1 LDG/thread over first 128B (L1/L2-shared).
    // int32-bool values are 0/1 => any nonzero byte above byte-0 => byte layout.
    const unsigned int v0 = ((const unsigned int*)true_ids_raw)[lane];

    // ---- (3) other cooperative loads (contiguous, few wavefronts) ----
    if (t < 512) {   // w2: 2048 floats as float4 into padded-stride shared
        const float4 wv = ((const float4*)w2)[t];
        const int hh = t >> 6, c4 = t & 63;
        *(float4*)&w2s[hh * W2STR + c4 * 4] = wv;
    }
    else if (t < 512 + 64) {  // b2: 256 floats as float4
        ((float4*)b2s)[t - 512] = ((const float4*)b2)[t - 512];
    }
    else if (t < 576 + HID) { w1s[t - 576] = w1[t - 576]; b1s[t - 576] = b1[t - 576]; }
    else if (t >= 640 && t - 640 < nj) ts[t - 640] = times[b * LEN + j0 + (t - 640)];

    int len_pref = 0;   // only g==0 stores output; avoid 2048 junk LDGs
    if (t < 128) {
        const int hw = __ldg(&lengths_i32[1]);   // hi word 0 <=> int64 (lengths >= 1)
        len_pref = (hw == 0) ? __ldg(&lengths_i32[2 * b]) : __ldg(&lengths_i32[b]);
    }

    // ---- resolve detection, fetch mask byte, select, store feats ----
    const bool byte_layout =
        __ballot_sync(0xFFFFFFFFu, (v0 & 0xFFFFFF00u) != 0u) != 0u;
    if (do_feat) {
        // LSB byte of an int32 bool equals its value (little-endian)
        const int bidx = (b * LEN + j_f) << (byte_layout ? 0 : 2);
        if (((const unsigned char*)true_ids_raw)[bidx] == 0)
            fv = make_float4(0.f, 0.f, 0.f, 0.f);
        ((float4*)feats)[t] = fv;
    }
    __syncthreads();   // feats, ts, w1s, b2s, w2s visible

    // per-thread w2 column from shared (conflict-free: 16h offset splits halves)
    float w2col[IN_CH];
    #pragma unroll
    for (int i = 0; i < IN_CH; i++)
        w2col[i] = w2s[h * W2STR + i * 16 + o];

    // ---- phase 1 row-dot (shared by both paths) ----
    auto p1row = [&](int jr) {
        const float4* fj4 = (const float4*)&feats[jr * IN_CH];
        float4 fa = fj4[0], fb = fj4[1], fc = fj4[2], fd = fj4[3];
        float aA = 0.0f, aB = 0.0f;
        aA = fmaf(fa.x, w2col[0], aA); aB = fmaf(fb.x, w2col[4], aB);
        aA = fmaf(fa.y, w2col[1], aA); aB = fmaf(fb.y, w2col[5], aB);
        aA = fmaf(fa.z, w2col[2], aA); aB = fmaf(fb.z, w2col[6], aB);
        aA = fmaf(fa.w, w2col[3], aA); aB = fmaf(fb.w, w2col[7], aB);
        aA = fmaf(fc.x, w2col[8],  aA); aB = fmaf(fd.x, w2col[12], aB);
        aA = fmaf(fc.y, w2col[9],  aA); aB = fmaf(fd.y, w2col[13], aB);
        aA = fmaf(fc.z, w2col[10], aA); aB = fmaf(fd.z, w2col[14], aB);
        aA = fmaf(fc.w, w2col[11], aA); aB = fmaf(fd.w, w2col[15], aB);
        fw2s[jr * JSTR + o * OSTR + h] = aA + aB;
        if (h == (jr & 7)) {               // one o-row of threads per jr does FB2
            float bA = 0.0f, bB = 0.0f;
            bA = fmaf(fa.x, b2s[0 * 16 + o],  bA); bB = fmaf(fb.x, b2s[4 * 16 + o],  bB);
            bA = fmaf(fa.y, b2s[1 * 16 + o],  bA); bB = fmaf(fb.y, b2s[5 * 16 + o],  bB);
            bA = fmaf(fa.z, b2s[2 * 16 + o],  bA); bB = fmaf(fb.z, b2s[6 * 16 + o],  bB);
            bA = fmaf(fa.w, b2s[3 * 16 + o],  bA); bB = fmaf(fb.w, b2s[7 * 16 + o],  bB);
            bA = fmaf(fc.x, b2s[8 * 16 + o],  bA); bB = fmaf(fd.x, b2s[12 * 16 + o], bB);
            bA = fmaf(fc.y, b2s[9 * 16 + o],  bA); bB = fmaf(fd.y, b2s[13 * 16 + o], bB);
            bA = fmaf(fc.z, b2s[10 * 16 + o], bA); bB = fmaf(fd.z, b2s[14 * 16 + o], bB);
            bA = fmaf(fc.w, b2s[11 * 16 + o], bA); bB = fmaf(fd.w, b2s[15 * 16 + o], bB);
            fw2s[jr * JSTR + o * OSTR + 8] = bA + bB;
        }
    };

    // ---- phase 2 band element (shared by both paths) ----
    float acc0 = 0.0f, acc1 = 0.0f;
    float w1r[HID], b1r[HID];
    #pragma unroll
    for (int k = 0; k < HID; k++) { w1r[k] = w1s[k]; b1r[k] = b1s[k]; }
    auto p2elem = [&](float tl, int jr) {
        const float dt = tl - ts[jr];
        const float* frp = &fw2s[jr * JSTR + o * OSTR];
        const float4 fA = *(const float4*)frp;        // FW2 h=0..3
        const float4 fB = *(const float4*)(frp + 4);  // FW2 h=4..7
        float a0 = frp[8];                            // FB2 term
        float a1 = 0.0f;
        float hv;
        hv = fmaf(dt, w1r[0], b1r[0]); hv = hv > 0.f ? hv : 0.f; a0 = fmaf(hv, fA.x, a0);
        hv = fmaf(dt, w1r[1], b1r[1]); hv = hv > 0.f ? hv : 0.f; a1 = fmaf(hv, fA.y, a1);
        hv = fmaf(dt, w1r[2], b1r[2]); hv = hv > 0.f ? hv : 0.f; a0 = fmaf(hv, fA.z, a0);
        hv = fmaf(dt, w1r[3], b1r[3]); hv = hv > 0.f ? hv : 0.f; a1 = fmaf(hv, fA.w, a1);
        hv = fmaf(dt, w1r[4], b1r[4]); hv = hv > 0.f ? hv : 0.f; a0 = fmaf(hv, fB.x, a0);
        hv = fmaf(dt, w1r[5], b1r[5]); hv = hv > 0.f ? hv : 0.f; a1 = fmaf(hv, fB.y, a1);
        hv = fmaf(dt, w1r[6], b1r[6]); hv = hv > 0.f ? hv : 0.f; a0 = fmaf(hv, fB.z, a0);
        hv = fmaf(dt, w1r[7], b1r[7]); hv = hv > 0.f ? hv : 0.f; a1 = fmaf(hv, fB.w, a1);
        acc0 += a0; acc1 += a1;
    };

    if (FULL) {
        // ---- phase 1: rows 0..36; g<7 -> 5 rows unconditional, g==7 -> rows 35,36 ----
        if (g < 7) {
            const int jr_base = g * 5;
            #pragma unroll
            for (int u = 0; u < 5; u++) p1row(jr_base + u);
        } else {
            p1row(35); p1row(36);
        }
        __syncthreads();

        // ---- phase 2: band exactly [h, h+29]; g<7 -> 4 elems, g==7 -> 2 ----
        const float tl = ts[h + (BAND - 1)];
        const int js = h + g * 4;
        if (g < 7) {
            p2elem(tl, js);     p2elem(tl, js + 1);
            p2elem(tl, js + 2); p2elem(tl, js + 3);
        } else {
            p2elem(tl, js);     p2elem(tl, js + 1);
        }
    } else {
        // ---- generic edge path (blockIdx.x < 4): j0 == 0, nj = l_start+8 ----
        {
            const int q = (nj + NGRP - 1) >> 3;
            const int jrA = g * q;
            int jrB = jrA + q; if (jrB > nj) jrB = nj;
            for (int jr = jrA; jr < jrB; jr++) p1row(jr);
        }
        __syncthreads();

        const int lr = l_start + h;           // j0 == 0
        const float tl = ts[lr];
        int jr_lo = lr - (BAND - 1); if (jr_lo < 0) jr_lo = 0;
        const int js = jr_lo + g * 4;
        #pragma unroll
        for (int u = 0; u < 4; u++) {
            const int jr = js + u;
            if (jr <= lr) p2elem(tl, jr);
        }
    }
    float acc = acc0 + acc1;

    if (g > 0) partial[(g - 1) * 128 + m] = acc;
    __syncthreads();

    if (g == 0) {
        float p0 = partial[m]           + partial[128 + m];
        float p1 = partial[2 * 128 + m] + partial[3 * 128 + m];
        float p2 = partial[4 * 128 + m] + partial[5 * 128 + m];
        acc += (p0 + p1) + (p2 + partial[6 * 128 + m]);
        const int l = l_start + h;
        const bool valid = l <= 6 * (len_pref - 1);
        out[(b * LEN + l) * OUT_CH + o] = valid ? acc : 0.0f;
    }
}

extern "C" void kernel_launch(void* const* d_in, const int* in_sizes, int n_in,
                              void* d_out, int out_size) {
    using namespace cc;
    // dict order: times, features, lengths, true_ids, [sim_size], w1, b1, w2, b2
    const float* times    = (const float*)d_in[0];
    const float* features = (const float*)d_in[1];
    const int*   lengths  = (const int*)d_in[2];
    const void*  tids     = d_in[3];

    int base = 4;
    if (n_in >= 9 && in_sizes[4] == 1) base = 5;  // sim_size scalar occupies slot 4

    const float* w1 = (const float*)d_in[base + 0];
    const float* b1 = (const float*)d_in[base + 1];
    const float* w2 = (const float*)d_in[base + 2];
    const float* b2 = (const float*)d_in[base + 3];
    float*       out = (float*)d_out;

    dim3 grid(LEN / TILE_L, BSZ);   // 64 x 2 = 128 blocks, 1 per SM
    cc1d_fused_kernel<<<grid, NTHR>>>(times, features, lengths, tids,
                                      w1, b1, w2, b2, out);
}